// round 2
// baseline (speedup 1.0000x reference)
#include <cuda_runtime.h>
#include <math.h>

#define T_LEN 4096
#define NB 2
#define DIM 512
#define CD 14
#define CS 16384
#define NTOK (NB * T_LEN)   // 8192

// ---------------- scratch (no allocations allowed) ----------------
__device__ float  g_avg_prob[CS];
__device__ int    g_occ[CS];
__device__ int    g_idx[NTOK];
__device__ double g_ent;
__device__ double g_commit;

// ---------------- K0: zero scratch (graph replays need fresh state) ----------------
__global__ void k_zero() {
    int i = blockIdx.x * blockDim.x + threadIdx.x;
    if (i < CS) { g_avg_prob[i] = 0.0f; g_occ[i] = 0; }
    if (i == 0) { g_ent = 0.0; g_commit = 0.0; }
}

// ---------------- K1: fused in-projection + per-token stats ----------------
// Grid: 256 blocks x 512 threads. Each block: 32 tokens, 16 c-groups of 32 channels.
#define TPB 32
#define CG  16
#define CPT (DIM / CG)       // 32
#define NTHR (TPB * CG)      // 512

__global__ __launch_bounds__(NTHR) void k_main(
    const float* __restrict__ z_e,   // (B, DIM, T)
    const float* __restrict__ W_in,  // (CD, DIM)
    const float* __restrict__ b_in)  // (CD,)
{
    // One 32KB buffer, time-multiplexed:
    //   phase A: Ws   = buf[0 .. 8192)          W_in transposed+padded [c*16 + d]
    //   phase B: part = buf[0 .. CG*TPB*CD)     per c-group partials (7168 floats)
    //            xs   = buf[7232 .. 7232+448)   reduced x per token
    __shared__ float buf[DIM * 16];
    float* Ws   = buf;
    float* part = buf;
    float* xs   = buf + 7232;

    const int tid = threadIdx.x;

    // cooperative load of W_in into padded-transposed smem
    for (int i = tid; i < DIM * 16; i += NTHR) {
        int c = i >> 4, d = i & 15;
        Ws[i] = (d < CD) ? W_in[d * DIM + c] : 0.0f;
    }
    __syncthreads();

    const int u = tid & 31;          // token lane
    const int g = tid >> 5;          // c-group
    const int tok0 = blockIdx.x * TPB;
    const int b = tok0 >> 12;
    const int tbase = tok0 & (T_LEN - 1);
    const float* zp = z_e + (size_t)b * DIM * T_LEN + tbase + u;

    float acc[CD];
#pragma unroll
    for (int d = 0; d < CD; d++) acc[d] = 0.0f;

    const int c0 = g * CPT;
#pragma unroll 4
    for (int cc = 0; cc < CPT; cc++) {
        int c = c0 + cc;
        float z = __ldg(zp + (size_t)c * T_LEN);
        const float4* w4 = reinterpret_cast<const float4*>(&Ws[c << 4]);
        float4 wa = w4[0], wb = w4[1], wc = w4[2], wd = w4[3];
        acc[0]  += z * wa.x;  acc[1]  += z * wa.y;  acc[2]  += z * wa.z;  acc[3]  += z * wa.w;
        acc[4]  += z * wb.x;  acc[5]  += z * wb.y;  acc[6]  += z * wb.z;  acc[7]  += z * wb.w;
        acc[8]  += z * wc.x;  acc[9]  += z * wc.y;  acc[10] += z * wc.z;  acc[11] += z * wc.w;
        acc[12] += z * wd.x;  acc[13] += z * wd.y;
    }
    __syncthreads();   // everyone done reading Ws; buffer is reused as part/xs

    {
        float* pr = &part[(g * TPB + u) * CD];
#pragma unroll
        for (int d = 0; d < CD; d++) pr[d] = acc[d];
    }
    __syncthreads();

    // deterministic reduction across the 16 c-groups
    for (int i = tid; i < TPB * CD; i += NTHR) {
        float s = 0.0f;
#pragma unroll
        for (int gg = 0; gg < CG; gg++) s += part[gg * TPB * CD + i];
        xs[i] = s + __ldg(&b_in[i % CD]);
    }
    __syncthreads();

    // warp 0: per-token stats (token = tok0 + tid)
    if (tid < TPB) {
        const int tok = tok0 + tid;
        float x[CD];
#pragma unroll
        for (int d = 0; d < CD; d++) x[d] = xs[tid * CD + d];

        // pack sign bits MSB-first (x > 0 strictly, else -1)
        int idx = 0;
#pragma unroll
        for (int d = 0; d < CD; d++)
            if (x[d] > 0.0f) idx |= (1 << (13 - d));
        g_idx[tok] = idx;
        g_occ[idx] = 1;

        // commitment loss contribution
        float cm = 0.0f;
#pragma unroll
        for (int d = 0; d < CD; d++) {
            float s = (x[d] > 0.0f) ? 1.0f : -1.0f;
            float df = x[d] - s;
            cm += df * df;
        }

        // factorized per-sample entropy + soft-dim collection
        float ent = 0.0f;
        float p0 = 1.0f;
        float ev[CD];
        int bp[CD];
        int m = 0;
#pragma unroll
        for (int d = 0; d < CD; d++) {
            float t = 400.0f * fabsf(x[d]);
            float e = expf(-t);                 // = q/(1-q), never overflows
            p0 *= 1.0f / (1.0f + e);
            ent += log1pf(e) + t * e / (1.0f + e);   // H(sigmoid(t)), stable
            if (e >= 1e-8f) { ev[m] = e; bp[m] = 1 << (13 - d); m++; }
        }

        // scatter significant codebook probabilities
        const int nsub = 1 << m;
        for (int s = 0; s < nsub; s++) {
            float p = p0;
            int code = idx;
            for (int j = 0; j < m; j++)
                if ((s >> j) & 1) { p *= ev[j]; code ^= bp[j]; }
            atomicAdd(&g_avg_prob[code], p);
        }

        // warp-reduce commit & entropy, one double atomic each
#pragma unroll
        for (int off = 16; off > 0; off >>= 1) {
            cm  += __shfl_down_sync(0xffffffffu, cm,  off);
            ent += __shfl_down_sync(0xffffffffu, ent, off);
        }
        if (tid == 0) {
            atomicAdd(&g_ent, (double)ent);
            atomicAdd(&g_commit, (double)cm);
        }
    }
}

// ---------------- K2: z_q writeout ----------------
// out[b,c,t] = b_out[c] + sum_d sgn_d * W_out[c,d]; sign flip via XOR of fp sign bit.
__global__ __launch_bounds__(256) void k_out(
    const float* __restrict__ W_out,  // (DIM, CD)
    const float* __restrict__ b_out,  // (DIM,)
    float* __restrict__ out)
{
    const int e = blockIdx.x * 256 + threadIdx.x;   // [0, 1048576)
    const int tq = e & 1023;
    const int c  = (e >> 10) & 511;
    const int b  = e >> 19;
    const int t  = tq << 2;

    const int4 iv = *reinterpret_cast<const int4*>(&g_idx[b * T_LEN + t]);
    int id[4] = { iv.x, iv.y, iv.z, iv.w };

    int wi[CD];
#pragma unroll
    for (int d = 0; d < CD; d++) wi[d] = __float_as_int(__ldg(&W_out[c * CD + d]));
    const float bc = __ldg(&b_out[c]);

    float r[4];
#pragma unroll
    for (int j = 0; j < 4; j++) {
        const unsigned nix = ~(unsigned)id[j];
        float s = bc;
#pragma unroll
        for (int d = 0; d < CD; d++) {
            // bit(13-d)==1 -> +w ; ==0 -> -w  (move bit 13-d to bit 31 of ~idx)
            unsigned sgn = (nix << (18 + d)) & 0x80000000u;
            s += __int_as_float((unsigned)wi[d] ^ sgn);
        }
        r[j] = s;
    }

    float4* op = reinterpret_cast<float4*>(&out[((size_t)(b * DIM + c)) * T_LEN + t]);
    *op = make_float4(r[0], r[1], r[2], r[3]);
}

// ---------------- K3: finalize scalars ----------------
__global__ void k_final(float* __restrict__ out, int out_size) {
    __shared__ double sh[256];
    __shared__ int shc[256];
    const int tid = threadIdx.x;
    double cbe = 0.0;
    int cnt = 0;
    for (int i = tid; i < CS; i += 256) {
        float ap = g_avg_prob[i] * (1.0f / NTOK);
        float l = logf(fmaxf(ap, 1e-20f));
        cbe += (double)(-ap * l);
        cnt += g_occ[i];
    }
    sh[tid] = cbe; shc[tid] = cnt;
    __syncthreads();
    for (int s = 128; s > 0; s >>= 1) {
        if (tid < s) { sh[tid] += sh[tid + s]; shc[tid] += shc[tid + s]; }
        __syncthreads();
    }
    if (tid == 0) {
        double pse = g_ent / (double)NTOK;
        double commit = g_commit / (double)(NTOK * CD);
        double aux = 0.1 * (pse - sh[0]) + 0.25 * commit;
        out[out_size - 2] = (float)aux;
        out[out_size - 1] = (float)shc[0] / (float)CS;
    }
}

// ---------------- launch ----------------
extern "C" void kernel_launch(void* const* d_in, const int* in_sizes, int n_in,
                              void* d_out, int out_size) {
    const float* z_e   = (const float*)d_in[0];
    const float* W_in  = (const float*)d_in[1];
    const float* b_in  = (const float*)d_in[2];
    const float* W_out = (const float*)d_in[3];
    const float* b_out = (const float*)d_in[4];
    float* out = (float*)d_out;

    k_zero<<<(CS + 255) / 256, 256>>>();
    k_main<<<NTOK / TPB, NTHR>>>(z_e, W_in, b_in);
    k_out<<<(NB * DIM * T_LEN / 4) / 256, 256>>>(W_out, b_out, out);
    k_final<<<1, 256>>>(out, out_size);
}

// round 3
// speedup vs baseline: 1.3526x; 1.3526x over previous
#include <cuda_runtime.h>
#include <math.h>

#define T_LEN 4096
#define NB 2
#define DIM 512
#define CD 14
#define CS 16384
#define NTOK (NB * T_LEN)   // 8192

// ---------------- scratch (no allocations allowed) ----------------
__device__ float  g_avg_prob[CS];
__device__ int    g_occ[CS];
__device__ int    g_idx[NTOK];
__device__ double g_ent;
__device__ double g_commit;
__device__ double g_cbe;     // codebook entropy partial sum
__device__ int    g_occn;    // number of occupied codes

// ---------------- K0: zero scratch (graph replays need fresh state) ----------------
__global__ void k_zero() {
    int i = blockIdx.x * blockDim.x + threadIdx.x;
    if (i < CS) { g_avg_prob[i] = 0.0f; g_occ[i] = 0; }
    if (i == 0) { g_ent = 0.0; g_commit = 0.0; g_cbe = 0.0; g_occn = 0; }
}

// ---------------- K1: fused in-projection + per-token stats ----------------
// Grid: 256 blocks x 512 threads. Each block: 32 tokens, 16 c-groups of 32 channels.
#define TPB 32
#define CG  16
#define CPT (DIM / CG)       // 32
#define NTHR (TPB * CG)      // 512

__global__ __launch_bounds__(NTHR) void k_main(
    const float* __restrict__ z_e,   // (B, DIM, T)
    const float* __restrict__ W_in,  // (CD, DIM)
    const float* __restrict__ b_in)  // (CD,)
{
    // One 32KB buffer, time-multiplexed:
    //   phase A: Ws   = buf[0 .. 8192)          W_in transposed+padded [c*16 + d]
    //   phase B: part = buf[0 .. CG*TPB*CD)     per c-group partials (7168 floats)
    //            xs   = buf[7232 .. 7232+448)   reduced x per token
    __shared__ float buf[DIM * 16];
    float* Ws   = buf;
    float* part = buf;
    float* xs   = buf + 7232;

    const int tid = threadIdx.x;

    // cooperative load of W_in into padded-transposed smem
    for (int i = tid; i < DIM * 16; i += NTHR) {
        int c = i >> 4, d = i & 15;
        Ws[i] = (d < CD) ? W_in[d * DIM + c] : 0.0f;
    }
    __syncthreads();

    const int u = tid & 31;          // token lane
    const int g = tid >> 5;          // c-group
    const int tok0 = blockIdx.x * TPB;
    const int b = tok0 >> 12;
    const int tbase = tok0 & (T_LEN - 1);
    const float* zp = z_e + (size_t)b * DIM * T_LEN + tbase + u;

    float acc[CD];
#pragma unroll
    for (int d = 0; d < CD; d++) acc[d] = 0.0f;

    const int c0 = g * CPT;
#pragma unroll 4
    for (int cc = 0; cc < CPT; cc++) {
        int c = c0 + cc;
        float z = __ldg(zp + (size_t)c * T_LEN);
        const float4* w4 = reinterpret_cast<const float4*>(&Ws[c << 4]);
        float4 wa = w4[0], wb = w4[1], wc = w4[2], wd = w4[3];
        acc[0]  += z * wa.x;  acc[1]  += z * wa.y;  acc[2]  += z * wa.z;  acc[3]  += z * wa.w;
        acc[4]  += z * wb.x;  acc[5]  += z * wb.y;  acc[6]  += z * wb.z;  acc[7]  += z * wb.w;
        acc[8]  += z * wc.x;  acc[9]  += z * wc.y;  acc[10] += z * wc.z;  acc[11] += z * wc.w;
        acc[12] += z * wd.x;  acc[13] += z * wd.y;
    }
    __syncthreads();   // everyone done reading Ws; buffer is reused as part/xs

    {
        float* pr = &part[(g * TPB + u) * CD];
#pragma unroll
        for (int d = 0; d < CD; d++) pr[d] = acc[d];
    }
    __syncthreads();

    // deterministic reduction across the 16 c-groups
    for (int i = tid; i < TPB * CD; i += NTHR) {
        float s = 0.0f;
#pragma unroll
        for (int gg = 0; gg < CG; gg++) s += part[gg * TPB * CD + i];
        xs[i] = s + __ldg(&b_in[i % CD]);
    }
    __syncthreads();

    // warp 0: per-token stats (token = tok0 + tid)
    if (tid < TPB) {
        const int tok = tok0 + tid;
        float x[CD];
#pragma unroll
        for (int d = 0; d < CD; d++) x[d] = xs[tid * CD + d];

        // pack sign bits MSB-first (x > 0 strictly, else -1)
        int idx = 0;
#pragma unroll
        for (int d = 0; d < CD; d++)
            if (x[d] > 0.0f) idx |= (1 << (13 - d));
        g_idx[tok] = idx;
        g_occ[idx] = 1;

        // commitment loss contribution
        float cm = 0.0f;
#pragma unroll
        for (int d = 0; d < CD; d++) {
            float s = (x[d] > 0.0f) ? 1.0f : -1.0f;
            float df = x[d] - s;
            cm += df * df;
        }

        // factorized per-sample entropy + soft-dim collection
        float ent = 0.0f;
        float p0 = 1.0f;
        float ev[CD];
        int bp[CD];
        int m = 0;
#pragma unroll
        for (int d = 0; d < CD; d++) {
            float t = 400.0f * fabsf(x[d]);
            float e = expf(-t);                 // = q/(1-q), never overflows
            p0 *= 1.0f / (1.0f + e);
            ent += log1pf(e) + t * e / (1.0f + e);   // H(sigmoid(t)), stable
            if (e >= 1e-8f) { ev[m] = e; bp[m] = 1 << (13 - d); m++; }
        }

        // scatter significant codebook probabilities
        const int nsub = 1 << m;
        for (int s = 0; s < nsub; s++) {
            float p = p0;
            int code = idx;
            for (int j = 0; j < m; j++)
                if ((s >> j) & 1) { p *= ev[j]; code ^= bp[j]; }
            atomicAdd(&g_avg_prob[code], p);
        }

        // warp-reduce commit & entropy, one double atomic each
#pragma unroll
        for (int off = 16; off > 0; off >>= 1) {
            cm  += __shfl_down_sync(0xffffffffu, cm,  off);
            ent += __shfl_down_sync(0xffffffffu, ent, off);
        }
        if (tid == 0) {
            atomicAdd(&g_ent, (double)ent);
            atomicAdd(&g_commit, (double)cm);
        }
    }
}

// ---------------- K2: z_q writeout + parallel codebook-entropy reduction ----------------
// out[b,c,t] = b_out[c] + sum_d sgn_d * W_out[c,d]; sign flip via XOR of fp sign bit.
// Blocks 0..63 additionally reduce 256 codebook entries each (g_avg_prob is final:
// this kernel launches after k_main completes in stream order).
__global__ __launch_bounds__(256) void k_out(
    const float* __restrict__ W_out,  // (DIM, CD)
    const float* __restrict__ b_out,  // (DIM,)
    float* __restrict__ out)
{
    __shared__ double sh[256];
    __shared__ int    shc[256];

    const int tid = threadIdx.x;
    const int e = blockIdx.x * 256 + tid;           // [0, 1048576)
    const int tq = e & 1023;
    const int c  = (e >> 10) & 511;
    const int b  = e >> 19;
    const int t  = tq << 2;

    const int4 iv = *reinterpret_cast<const int4*>(&g_idx[b * T_LEN + t]);
    int id[4] = { iv.x, iv.y, iv.z, iv.w };

    int wi[CD];
#pragma unroll
    for (int d = 0; d < CD; d++) wi[d] = __float_as_int(__ldg(&W_out[c * CD + d]));
    const float bc = __ldg(&b_out[c]);

    float r[4];
#pragma unroll
    for (int j = 0; j < 4; j++) {
        const unsigned nix = ~(unsigned)id[j];
        float s = bc;
#pragma unroll
        for (int d = 0; d < CD; d++) {
            // bit(13-d)==1 -> +w ; ==0 -> -w  (move bit 13-d to bit 31 of ~idx)
            unsigned sgn = (nix << (18 + d)) & 0x80000000u;
            s += __int_as_float((unsigned)wi[d] ^ sgn);
        }
        r[j] = s;
    }

    float4* op = reinterpret_cast<float4*>(&out[((size_t)(b * DIM + c)) * T_LEN + t]);
    *op = make_float4(r[0], r[1], r[2], r[3]);

    // ---- codebook entropy + occupancy: 64 blocks x 256 threads cover CS ----
    if (blockIdx.x < 64) {
        const int i = blockIdx.x * 256 + tid;
        float ap = g_avg_prob[i] * (1.0f / NTOK);
        float l  = logf(fmaxf(ap, 1e-20f));
        sh[tid]  = (double)(-ap * l);
        shc[tid] = g_occ[i];
        __syncthreads();
        for (int s = 128; s > 0; s >>= 1) {
            if (tid < s) { sh[tid] += sh[tid + s]; shc[tid] += shc[tid + s]; }
            __syncthreads();
        }
        if (tid == 0) {
            atomicAdd(&g_cbe, sh[0]);
            atomicAdd(&g_occn, shc[0]);
        }
    }
}

// ---------------- K3: tiny scalar finalize ----------------
__global__ void k_final(float* __restrict__ out, int out_size) {
    if (threadIdx.x == 0) {
        double pse = g_ent / (double)NTOK;
        double commit = g_commit / (double)(NTOK * CD);
        double aux = 0.1 * (pse - g_cbe) + 0.25 * commit;
        out[out_size - 2] = (float)aux;
        out[out_size - 1] = (float)g_occn / (float)CS;
    }
}

// ---------------- launch ----------------
extern "C" void kernel_launch(void* const* d_in, const int* in_sizes, int n_in,
                              void* d_out, int out_size) {
    const float* z_e   = (const float*)d_in[0];
    const float* W_in  = (const float*)d_in[1];
    const float* b_in  = (const float*)d_in[2];
    const float* W_out = (const float*)d_in[3];
    const float* b_out = (const float*)d_in[4];
    float* out = (float*)d_out;

    k_zero<<<(CS + 255) / 256, 256>>>();
    k_main<<<NTOK / TPB, NTHR>>>(z_e, W_in, b_in);
    k_out<<<(NB * DIM * T_LEN / 4) / 256, 256>>>(W_out, b_out, out);
    k_final<<<1, 32>>>(out, out_size);
}